// round 13
// baseline (speedup 1.0000x reference)
#include <cuda_runtime.h>
#include <math.h>

#define BB 16
#define NN 65536
#define CC 21
#define NCLS 20
#define SLICES (BB*NCLS)
#define TOPK 200
#define WSEL 512            // selection window target; exact top-200 provably inside
#define TH_CONF 0.05f
#define CBUF 2048
#define NBIN 128

// Static scratch (no runtime allocation).
__device__ __align__(16) unsigned char g_bins[(size_t)SLICES * NN];  // 21 MB u8 bin image
__device__ unsigned g_hist[SLICES * NBIN];
__device__ int g_scnt[SLICES];
__device__ unsigned g_sv[SLICES * CBUF];

// ---------------------------------------------------------------------------
// XLA-GPU-replica softmax sum over 21 exps (proven bit-exact rounds 5-12).
// ---------------------------------------------------------------------------
__device__ __forceinline__ float tree_sum21(const float* e) {
    float b0 = __fadd_rn(__fadd_rn(e[0],  e[16]), e[8]);
    float b1 = __fadd_rn(__fadd_rn(e[1],  e[17]), e[9]);
    float b2 = __fadd_rn(__fadd_rn(e[2],  e[18]), e[10]);
    float b3 = __fadd_rn(__fadd_rn(e[3],  e[19]), e[11]);
    float b4 = __fadd_rn(__fadd_rn(e[4],  e[20]), e[12]);
    float b5 = __fadd_rn(e[5],  e[13]);
    float b6 = __fadd_rn(e[6],  e[14]);
    float b7 = __fadd_rn(e[7],  e[15]);
    float c0 = __fadd_rn(b0, b4);
    float c1 = __fadd_rn(b1, b5);
    float c2 = __fadd_rn(b2, b6);
    float c3 = __fadd_rn(b3, b7);
    float d0 = __fadd_rn(c0, c2);
    float d1 = __fadd_rn(c1, c3);
    return __fadd_rn(d0, d1);
}

__device__ __forceinline__ float rcp_approx(float x) {
    float r;
    asm("rcp.approx.f32 %0, %1;" : "=f"(r) : "f"(x));
    return r;
}

// Schraudolph exp: 1 FFMA + 1 CVT, rel err ~ +/-3%. Screening only.
__device__ __forceinline__ float exp_fast(float x) {
    int i = __float2int_rn(fmaf(x, 12102203.0f, 1064993216.0f));
    return __int_as_float(i);
}

__global__ void k_zero() {
    int t = blockIdx.x * blockDim.x + threadIdx.x;
    if (t < SLICES * NBIN) g_hist[t] = 0;
    if (t < SLICES) g_scnt[t] = 0;
}

// ---------------------------------------------------------------------------
// Kernel 1: approx softmax -> u8 bin image (NO inline hist — that cost ~35us
// of smem-atomic serialization in rounds 10/12). bin mapping proven:
// bin = clamp((v16 - 0x3D00) >> 3, 0..127); bin 0 (p~ < 0.0334) is "don't
// care" (exact-valid entries have p~ >= 0.047 -> bin >= 8).
// ---------------------------------------------------------------------------
__global__ void k_score(const float* __restrict__ conf) {
    __shared__ __align__(16) float s[256 * CC];                 // 21504 B
    __shared__ __align__(16) unsigned char sb8[NCLS][256];      // 5120 B
    const int bpb = NN / 256;
    int b  = blockIdx.x / bpb;
    int a0 = (blockIdx.x % bpb) * 256;

    const float4* src = reinterpret_cast<const float4*>(conf + ((size_t)b * NN + a0) * CC);
    float4* ds = reinterpret_cast<float4*>(s);
    #pragma unroll
    for (int j = threadIdx.x; j < 256 * CC / 4; j += 256) ds[j] = src[j];
    __syncthreads();

    int t = threadIdx.x;
    float e[CC];
    float sum = 0.f;
    #pragma unroll
    for (int c = 0; c < CC; c++) {
        e[c] = exp_fast(s[t * CC + c]);     // stride 21: conflict-free
        sum += e[c];
    }
    float rinv = rcp_approx(sum);
    #pragma unroll
    for (int c = 1; c < CC; c++) {
        unsigned v16 = __float_as_uint(e[c] * rinv) >> 16;
        unsigned bin = 0;
        if (v16 >= 0x3D08u) {
            bin = (v16 - 0x3D00u) >> 3;
            if (bin > 127u) bin = 127u;
        }
        sb8[c - 1][t] = (unsigned char)bin;
    }
    __syncthreads();

    // copy-out bin image: 20 rows x 256 B = 320 uint4, coalesced
    const uint4* sbv = reinterpret_cast<const uint4*>(sb8);
    for (int k = threadIdx.x; k < NCLS * 16; k += 256) {
        int row = k >> 4, off = k & 15;
        int slice = b * NCLS + row;
        reinterpret_cast<uint4*>(g_bins + (size_t)slice * NN + a0)[off] = sbv[k];
    }
}

// ---------------------------------------------------------------------------
// Kernel 1b: histogram pass over the bin image. 8 chunk-blocks per slice
// (same decomposition as k_collect). Skip zero bytes (~60%).
// ---------------------------------------------------------------------------
__global__ void k_hist() {
    int bid = blockIdx.x;
    int slice = bid >> 3, chunk = bid & 7;
    int t = threadIdx.x;

    __shared__ unsigned hist[NBIN];
    if (t < NBIN) hist[t] = 0;
    __syncthreads();

    const uint4* bv = reinterpret_cast<const uint4*>(g_bins + (size_t)slice * NN + chunk * 8192);
    for (int i = t; i < 512; i += 256) {
        uint4 q = bv[i];
        unsigned wds[4] = {q.x, q.y, q.z, q.w};
        #pragma unroll
        for (int h = 0; h < 4; h++) {
            unsigned w = wds[h];
            if (w) {
                #pragma unroll
                for (int byte = 0; byte < 4; byte++) {
                    unsigned bin = (w >> (byte * 8)) & 0xFFu;
                    if (bin) atomicAdd(&hist[bin], 1u);
                }
            }
        }
    }
    __syncthreads();

    if (t < NBIN && hist[t]) atomicAdd(&g_hist[slice * NBIN + t], hist[t]);
}

// ---------------------------------------------------------------------------
// Kernel 2 (round-12 verbatim, proven): survivor collection. 8 chunk-blocks
// per slice; 128-bin suffix scan -> vth (largest bin with suffix >= 512,
// floor 1); __vcmpgeu4 chunk scan; push survivor indices.
// ---------------------------------------------------------------------------
__global__ void k_collect() {
    int bid = blockIdx.x;
    int slice = bid >> 3, chunk = bid & 7;
    int t = threadIdx.x;

    __shared__ unsigned suf[NBIN];
    __shared__ int s_vth;

    if (t < NBIN) suf[t] = g_hist[slice * NBIN + t];
    if (t == 0) s_vth = 1;
    __syncthreads();
    for (int st = 1; st < NBIN; st <<= 1) {
        unsigned add = 0;
        if (t < NBIN && t + st < NBIN) add = suf[t + st];
        __syncthreads();
        if (t < NBIN) suf[t] += add;
        __syncthreads();
    }
    unsigned total = suf[1];
    unsigned target = total < WSEL ? total : WSEL;
    if (t >= 1 && t < NBIN && target > 0 && suf[t] >= target) atomicMax(&s_vth, t);
    __syncthreads();
    unsigned vth = (unsigned)s_vth;
    unsigned vth4 = vth * 0x01010101u;

    const uint4* bv = reinterpret_cast<const uint4*>(g_bins + (size_t)slice * NN + chunk * 8192);
    int base0 = chunk * 8192;
    for (int i = t; i < 512; i += 256) {
        uint4 q = bv[i];
        unsigned wds[4] = {q.x, q.y, q.z, q.w};
        #pragma unroll
        for (int h = 0; h < 4; h++) {
            unsigned m = __vcmpgeu4(wds[h], vth4);   // 0xFF per byte where bin >= vth
            while (m) {
                int byte = (__ffs(m) - 1) >> 3;
                int pos = atomicAdd(&g_scnt[slice], 1);
                if (pos < CBUF) g_sv[slice * CBUF + pos] = (unsigned)(base0 + i * 16 + h * 4 + byte);
                m &= ~(0xFFu << (byte * 8));
            }
        }
    }
}

// ---------------------------------------------------------------------------
// Kernel 3 (fused k_sel + k_nms, 512 threads; bodies proven in round 12):
//  (1) exact recompute of survivors (bit-exact pipeline, p>=0.05 threshold)
//  (2) bitonic sort u64 keys descending (score desc, idx asc)
//  (3) decode top-200 (bit-exact), triangle IoU bitmask (division-free exact
//      predicate), serial greedy scan, [200,5] output.
// ---------------------------------------------------------------------------
__global__ void k_selnms(const float* __restrict__ conf,
                         const float* __restrict__ loc,
                         const float* __restrict__ anchors,
                         float* __restrict__ out) {
    int slice = blockIdx.x;
    int b   = slice / NCLS;
    int cls = slice % NCLS + 1;
    int nt  = blockDim.x;

    __shared__ unsigned long long skeys[CBUF];   // 16 KB
    __shared__ float bx1[TOPK], by1[TOPK], bx2[TOPK], by2[TOPK], bar[TOPK], bsc[TOPK];
    __shared__ unsigned long long mat[TOPK * 4];
    __shared__ unsigned char keepA[TOPK];

    int S = g_scnt[slice];
    if (S > CBUF) S = CBUF;

    for (int t = threadIdx.x; t < S; t += nt) {
        int idx = (int)g_sv[slice * CBUF + t];
        const float* row = conf + ((size_t)b * NN + idx) * CC;
        float v[CC];
        #pragma unroll
        for (int c = 0; c < CC; c++) v[c] = row[c];
        float mx = v[0];
        #pragma unroll
        for (int c = 1; c < CC; c++) mx = fmaxf(mx, v[c]);
        float ex[CC];
        #pragma unroll
        for (int c = 0; c < CC; c++) ex[c] = expf(__fsub_rn(v[c], mx));
        float sum = tree_sum21(ex);
        float p = __fdiv_rn(ex[cls], sum);
        skeys[t] = (p >= TH_CONF)
            ? (((unsigned long long)__float_as_uint(p) << 16) |
               (unsigned long long)(65535 - idx))
            : 0ull;
    }
    int P = 256; while (P < S) P <<= 1;
    for (int i = S + threadIdx.x; i < P; i += nt) skeys[i] = 0ull;
    __syncthreads();

    // bitonic sort, descending
    for (int k = 2; k <= P; k <<= 1) {
        for (int j = k >> 1; j > 0; j >>= 1) {
            for (int i = threadIdx.x; i < P; i += nt) {
                int l = i ^ j;
                if (l > i) {
                    unsigned long long a = skeys[i], c = skeys[l];
                    bool desc = ((i & k) == 0);
                    if (desc ? (a < c) : (a > c)) { skeys[i] = c; skeys[l] = a; }
                }
            }
            __syncthreads();
        }
    }

    int T = __syncthreads_count((threadIdx.x < TOPK) && (skeys[threadIdx.x] != 0ull));

    // decode (bit-exact)
    for (int t = threadIdx.x; t < T; t += nt) {
        unsigned long long key = skeys[t];
        int idx = 65535 - (int)(key & 0xFFFFull);
        float sc = __uint_as_float((unsigned)(key >> 16));
        float4 l = reinterpret_cast<const float4*>(loc)[(size_t)b * NN + idx];
        float4 a = reinterpret_cast<const float4*>(anchors)[idx];
        float cx = __fadd_rn(a.x, __fmul_rn(__fmul_rn(l.x, 0.1f), a.z));
        float cy = __fadd_rn(a.y, __fmul_rn(__fmul_rn(l.y, 0.1f), a.w));
        float w  = __fmul_rn(a.z, expf(__fmul_rn(l.z, 0.2f)));
        float h  = __fmul_rn(a.w, expf(__fmul_rn(l.w, 0.2f)));
        float x1 = __fsub_rn(cx, __fmul_rn(0.5f, w));
        float y1 = __fsub_rn(cy, __fmul_rn(0.5f, h));
        float x2 = __fadd_rn(cx, __fmul_rn(0.5f, w));
        float y2 = __fadd_rn(cy, __fmul_rn(0.5f, h));
        bx1[t] = x1; by1[t] = y1; bx2[t] = x2; by2[t] = y2;
        bar[t] = __fmul_rn(fmaxf(__fsub_rn(x2, x1), 0.f),
                           fmaxf(__fsub_rn(y2, y1), 0.f));
        bsc[t] = sc;
    }
    __syncthreads();

    // upper triangle only: the greedy scan only consumes bits j > i
    for (int task = threadIdx.x; task < T * 4; task += nt) {
        int i = task >> 2, w = task & 3;
        unsigned long long bits = 0;
        int j0 = w * 64;
        int j1 = j0 + 64 < T ? j0 + 64 : T;
        int js = j0 > i + 1 ? j0 : i + 1;
        float x1i = bx1[i], y1i = by1[i], x2i = bx2[i], y2i = by2[i], ai = bar[i];
        for (int j = js; j < j1; j++) {
            float xx1 = fmaxf(x1i, bx1[j]);
            float yy1 = fmaxf(y1i, by1[j]);
            float xx2 = fminf(x2i, bx2[j]);
            float yy2 = fminf(y2i, by2[j]);
            float iw = fmaxf(__fsub_rn(xx2, xx1), 0.f);
            float ih = fmaxf(__fsub_rn(yy2, yy1), 0.f);
            float inter = __fmul_rn(iw, ih);
            float uni = __fsub_rn(__fadd_rn(ai, bar[j]), inter);
            float u = fmaxf(uni, 1e-9f);
            // exact: rn(inter/u) > 0.5  <=>  inter - 0.5u > u * 2^-25
            if (fmaf(-0.5f, u, inter) > u * 0x1p-25f)
                bits |= 1ull << (j - j0);
        }
        mat[i * 4 + w] = bits;
    }
    __syncthreads();

    if (threadIdx.x == 0) {
        unsigned long long s0 = 0, s1 = 0, s2 = 0, s3 = 0;
        for (int i = 0; i < T; i++) {
            unsigned long long sw = (i < 64) ? s0 : (i < 128) ? s1 : (i < 192) ? s2 : s3;
            bool kp = !((sw >> (i & 63)) & 1ull);
            keepA[i] = kp ? 1 : 0;
            if (kp) {
                s0 |= mat[i * 4 + 0];
                s1 |= mat[i * 4 + 1];
                s2 |= mat[i * 4 + 2];
                s3 |= mat[i * 4 + 3];
            }
        }
    }
    __syncthreads();

    float* o = out + (size_t)slice * TOPK * 5;
    for (int t = threadIdx.x; t < TOPK; t += nt) {
        bool kp = (t < T) && keepA[t];
        o[t * 5 + 0] = kp ? bx1[t] : 0.f;
        o[t * 5 + 1] = kp ? by1[t] : 0.f;
        o[t * 5 + 2] = kp ? bx2[t] : 0.f;
        o[t * 5 + 3] = kp ? by2[t] : 0.f;
        o[t * 5 + 4] = kp ? bsc[t] : 0.f;
    }
}

extern "C" void kernel_launch(void* const* d_in, const int* in_sizes, int n_in,
                              void* d_out, int out_size) {
    const float* conf    = (const float*)d_in[0];
    const float* loc     = (const float*)d_in[1];
    const float* anchors = (const float*)d_in[2];
    float* out = (float*)d_out;

    k_zero<<<(SLICES * NBIN + 255) / 256, 256>>>();
    k_score<<<(BB * NN) / 256, 256>>>(conf);
    k_hist<<<SLICES * 8, 256>>>();
    k_collect<<<SLICES * 8, 256>>>();
    k_selnms<<<SLICES, 512>>>(conf, loc, anchors, out);
}

// round 14
// speedup vs baseline: 1.1646x; 1.1646x over previous
#include <cuda_runtime.h>
#include <math.h>

#define BB 16
#define NN 65536
#define CC 21
#define NCLS 20
#define SLICES (BB*NCLS)
#define TOPK 200
#define WSEL 512            // selection window target; exact top-200 provably inside
#define TH_CONF 0.05f
#define CBUF 2048
#define NBIN 128

// Static scratch (no runtime allocation).
__device__ __align__(16) unsigned char g_bins[(size_t)SLICES * NN];  // 21 MB u8 bin image
__device__ unsigned g_hist[SLICES * NBIN];
__device__ int g_scnt[SLICES];
__device__ unsigned g_sv[SLICES * CBUF];

// ---------------------------------------------------------------------------
// XLA-GPU-replica softmax sum over 21 exps (proven bit-exact rounds 5-13).
// ---------------------------------------------------------------------------
__device__ __forceinline__ float tree_sum21(const float* e) {
    float b0 = __fadd_rn(__fadd_rn(e[0],  e[16]), e[8]);
    float b1 = __fadd_rn(__fadd_rn(e[1],  e[17]), e[9]);
    float b2 = __fadd_rn(__fadd_rn(e[2],  e[18]), e[10]);
    float b3 = __fadd_rn(__fadd_rn(e[3],  e[19]), e[11]);
    float b4 = __fadd_rn(__fadd_rn(e[4],  e[20]), e[12]);
    float b5 = __fadd_rn(e[5],  e[13]);
    float b6 = __fadd_rn(e[6],  e[14]);
    float b7 = __fadd_rn(e[7],  e[15]);
    float c0 = __fadd_rn(b0, b4);
    float c1 = __fadd_rn(b1, b5);
    float c2 = __fadd_rn(b2, b6);
    float c3 = __fadd_rn(b3, b7);
    float d0 = __fadd_rn(c0, c2);
    float d1 = __fadd_rn(c1, c3);
    return __fadd_rn(d0, d1);
}

__device__ __forceinline__ float rcp_approx(float x) {
    float r;
    asm("rcp.approx.f32 %0, %1;" : "=f"(r) : "f"(x));
    return r;
}

// Schraudolph exp: 1 FFMA + 1 CVT, rel err ~ +/-3%. Screening only.
__device__ __forceinline__ float exp_fast(float x) {
    int i = __float2int_rn(fmaf(x, 12102203.0f, 1064993216.0f));
    return __int_as_float(i);
}

__global__ void k_zero() {
    int t = blockIdx.x * blockDim.x + threadIdx.x;
    if (t < SLICES * NBIN) g_hist[t] = 0;
    if (t < SLICES) g_scnt[t] = 0;
}

// ---------------------------------------------------------------------------
// Kernel 1 (round-13 verbatim, proven): approx softmax -> u8 bin image.
// bin = clamp((v16 - 0x3D00) >> 3, 0..127); bin 0 is "don't care"
// (exact-valid entries have p~ >= 0.047 -> bin >= 8).
// ---------------------------------------------------------------------------
__global__ void k_score(const float* __restrict__ conf) {
    __shared__ __align__(16) float s[256 * CC];                 // 21504 B
    __shared__ __align__(16) unsigned char sb8[NCLS][256];      // 5120 B
    const int bpb = NN / 256;
    int b  = blockIdx.x / bpb;
    int a0 = (blockIdx.x % bpb) * 256;

    const float4* src = reinterpret_cast<const float4*>(conf + ((size_t)b * NN + a0) * CC);
    float4* ds = reinterpret_cast<float4*>(s);
    #pragma unroll
    for (int j = threadIdx.x; j < 256 * CC / 4; j += 256) ds[j] = src[j];
    __syncthreads();

    int t = threadIdx.x;
    float e[CC];
    float sum = 0.f;
    #pragma unroll
    for (int c = 0; c < CC; c++) {
        e[c] = exp_fast(s[t * CC + c]);     // stride 21: conflict-free
        sum += e[c];
    }
    float rinv = rcp_approx(sum);
    #pragma unroll
    for (int c = 1; c < CC; c++) {
        unsigned v16 = __float_as_uint(e[c] * rinv) >> 16;
        unsigned bin = 0;
        if (v16 >= 0x3D08u) {
            bin = (v16 - 0x3D00u) >> 3;
            if (bin > 127u) bin = 127u;
        }
        sb8[c - 1][t] = (unsigned char)bin;
    }
    __syncthreads();

    // copy-out bin image: 20 rows x 256 B = 320 uint4, coalesced
    const uint4* sbv = reinterpret_cast<const uint4*>(sb8);
    for (int k = threadIdx.x; k < NCLS * 16; k += 256) {
        int row = k >> 4, off = k & 15;
        int slice = b * NCLS + row;
        reinterpret_cast<uint4*>(g_bins + (size_t)slice * NN + a0)[off] = sbv[k];
    }
}

// ---------------------------------------------------------------------------
// Kernel 1b (round-13 verbatim): histogram pass over the bin image.
// 8 chunk-blocks per slice; skip zero bytes (~60%).
// ---------------------------------------------------------------------------
__global__ void k_hist() {
    int bid = blockIdx.x;
    int slice = bid >> 3, chunk = bid & 7;
    int t = threadIdx.x;

    __shared__ unsigned hist[NBIN];
    if (t < NBIN) hist[t] = 0;
    __syncthreads();

    const uint4* bv = reinterpret_cast<const uint4*>(g_bins + (size_t)slice * NN + chunk * 8192);
    for (int i = t; i < 512; i += 256) {
        uint4 q = bv[i];
        unsigned wds[4] = {q.x, q.y, q.z, q.w};
        #pragma unroll
        for (int h = 0; h < 4; h++) {
            unsigned w = wds[h];
            if (w) {
                #pragma unroll
                for (int byte = 0; byte < 4; byte++) {
                    unsigned bin = (w >> (byte * 8)) & 0xFFu;
                    if (bin) atomicAdd(&hist[bin], 1u);
                }
            }
        }
    }
    __syncthreads();

    if (t < NBIN && hist[t]) atomicAdd(&g_hist[slice * NBIN + t], hist[t]);
}

// ---------------------------------------------------------------------------
// Kernel 2 (REWORKED push path): survivor collection. 8 chunk-blocks per
// slice; 128-bin suffix scan -> vth (unchanged, proven); then per-iteration
// WARP-AGGREGATED push: vcmp+popc count -> warp shuffle scan -> ONE atomic
// per warp -> prefix-ordered writes. Survivor SET identical to rounds 12/13
// (same vth, same comparisons); only g_sv order changes, erased by the
// downstream total sort.
// ---------------------------------------------------------------------------
__global__ void k_collect() {
    int bid = blockIdx.x;
    int slice = bid >> 3, chunk = bid & 7;
    int t = threadIdx.x;
    unsigned lane = t & 31u;

    __shared__ unsigned suf[NBIN];
    __shared__ int s_vth;

    if (t < NBIN) suf[t] = g_hist[slice * NBIN + t];
    if (t == 0) s_vth = 1;
    __syncthreads();
    for (int st = 1; st < NBIN; st <<= 1) {
        unsigned add = 0;
        if (t < NBIN && t + st < NBIN) add = suf[t + st];
        __syncthreads();
        if (t < NBIN) suf[t] += add;
        __syncthreads();
    }
    unsigned total = suf[1];
    unsigned target = total < WSEL ? total : WSEL;
    if (t >= 1 && t < NBIN && target > 0 && suf[t] >= target) atomicMax(&s_vth, t);
    __syncthreads();
    unsigned vth = (unsigned)s_vth;
    unsigned vth4 = vth * 0x01010101u;

    const uint4* bv = reinterpret_cast<const uint4*>(g_bins + (size_t)slice * NN + chunk * 8192);
    int base0 = chunk * 8192;
    // exactly 2 uniform iterations for every thread -> full-mask shuffles safe
    for (int i = t; i < 512; i += 256) {
        uint4 q = bv[i];
        unsigned m0 = __vcmpgeu4(q.x, vth4);
        unsigned m1 = __vcmpgeu4(q.y, vth4);
        unsigned m2 = __vcmpgeu4(q.z, vth4);
        unsigned m3 = __vcmpgeu4(q.w, vth4);
        int cnt = (__popc(m0) + __popc(m1) + __popc(m2) + __popc(m3)) >> 3;

        // warp inclusive scan of cnt
        int inc = cnt;
        #pragma unroll
        for (int off = 1; off < 32; off <<= 1) {
            int v = __shfl_up_sync(0xffffffffu, inc, off);
            if ((int)lane >= off) inc += v;
        }
        int wtot = __shfl_sync(0xffffffffu, inc, 31);
        int excl = inc - cnt;

        int base = 0;
        if (lane == 31u && wtot > 0) base = atomicAdd(&g_scnt[slice], wtot);
        base = __shfl_sync(0xffffffffu, base, 31);

        if (cnt) {
            int pos = base + excl;
            unsigned ms[4] = {m0, m1, m2, m3};
            #pragma unroll
            for (int h = 0; h < 4; h++) {
                unsigned m = ms[h];
                while (m) {
                    int byte = (__ffs(m) - 1) >> 3;
                    if (pos < CBUF)
                        g_sv[slice * CBUF + pos] = (unsigned)(base0 + i * 16 + h * 4 + byte);
                    pos++;
                    m &= ~(0xFFu << (byte * 8));
                }
            }
        }
    }
}

// ---------------------------------------------------------------------------
// Kernel 3 (round-13 verbatim, proven): fused k_sel + k_nms, 512 threads.
// ---------------------------------------------------------------------------
__global__ void k_selnms(const float* __restrict__ conf,
                         const float* __restrict__ loc,
                         const float* __restrict__ anchors,
                         float* __restrict__ out) {
    int slice = blockIdx.x;
    int b   = slice / NCLS;
    int cls = slice % NCLS + 1;
    int nt  = blockDim.x;

    __shared__ unsigned long long skeys[CBUF];   // 16 KB
    __shared__ float bx1[TOPK], by1[TOPK], bx2[TOPK], by2[TOPK], bar[TOPK], bsc[TOPK];
    __shared__ unsigned long long mat[TOPK * 4];
    __shared__ unsigned char keepA[TOPK];

    int S = g_scnt[slice];
    if (S > CBUF) S = CBUF;

    for (int t = threadIdx.x; t < S; t += nt) {
        int idx = (int)g_sv[slice * CBUF + t];
        const float* row = conf + ((size_t)b * NN + idx) * CC;
        float v[CC];
        #pragma unroll
        for (int c = 0; c < CC; c++) v[c] = row[c];
        float mx = v[0];
        #pragma unroll
        for (int c = 1; c < CC; c++) mx = fmaxf(mx, v[c]);
        float ex[CC];
        #pragma unroll
        for (int c = 0; c < CC; c++) ex[c] = expf(__fsub_rn(v[c], mx));
        float sum = tree_sum21(ex);
        float p = __fdiv_rn(ex[cls], sum);
        skeys[t] = (p >= TH_CONF)
            ? (((unsigned long long)__float_as_uint(p) << 16) |
               (unsigned long long)(65535 - idx))
            : 0ull;
    }
    int P = 256; while (P < S) P <<= 1;
    for (int i = S + threadIdx.x; i < P; i += nt) skeys[i] = 0ull;
    __syncthreads();

    // bitonic sort, descending
    for (int k = 2; k <= P; k <<= 1) {
        for (int j = k >> 1; j > 0; j >>= 1) {
            for (int i = threadIdx.x; i < P; i += nt) {
                int l = i ^ j;
                if (l > i) {
                    unsigned long long a = skeys[i], c = skeys[l];
                    bool desc = ((i & k) == 0);
                    if (desc ? (a < c) : (a > c)) { skeys[i] = c; skeys[l] = a; }
                }
            }
            __syncthreads();
        }
    }

    int T = __syncthreads_count((threadIdx.x < TOPK) && (skeys[threadIdx.x] != 0ull));

    // decode (bit-exact)
    for (int t = threadIdx.x; t < T; t += nt) {
        unsigned long long key = skeys[t];
        int idx = 65535 - (int)(key & 0xFFFFull);
        float sc = __uint_as_float((unsigned)(key >> 16));
        float4 l = reinterpret_cast<const float4*>(loc)[(size_t)b * NN + idx];
        float4 a = reinterpret_cast<const float4*>(anchors)[idx];
        float cx = __fadd_rn(a.x, __fmul_rn(__fmul_rn(l.x, 0.1f), a.z));
        float cy = __fadd_rn(a.y, __fmul_rn(__fmul_rn(l.y, 0.1f), a.w));
        float w  = __fmul_rn(a.z, expf(__fmul_rn(l.z, 0.2f)));
        float h  = __fmul_rn(a.w, expf(__fmul_rn(l.w, 0.2f)));
        float x1 = __fsub_rn(cx, __fmul_rn(0.5f, w));
        float y1 = __fsub_rn(cy, __fmul_rn(0.5f, h));
        float x2 = __fadd_rn(cx, __fmul_rn(0.5f, w));
        float y2 = __fadd_rn(cy, __fmul_rn(0.5f, h));
        bx1[t] = x1; by1[t] = y1; bx2[t] = x2; by2[t] = y2;
        bar[t] = __fmul_rn(fmaxf(__fsub_rn(x2, x1), 0.f),
                           fmaxf(__fsub_rn(y2, y1), 0.f));
        bsc[t] = sc;
    }
    __syncthreads();

    // upper triangle only: the greedy scan only consumes bits j > i
    for (int task = threadIdx.x; task < T * 4; task += nt) {
        int i = task >> 2, w = task & 3;
        unsigned long long bits = 0;
        int j0 = w * 64;
        int j1 = j0 + 64 < T ? j0 + 64 : T;
        int js = j0 > i + 1 ? j0 : i + 1;
        float x1i = bx1[i], y1i = by1[i], x2i = bx2[i], y2i = by2[i], ai = bar[i];
        for (int j = js; j < j1; j++) {
            float xx1 = fmaxf(x1i, bx1[j]);
            float yy1 = fmaxf(y1i, by1[j]);
            float xx2 = fminf(x2i, bx2[j]);
            float yy2 = fminf(y2i, by2[j]);
            float iw = fmaxf(__fsub_rn(xx2, xx1), 0.f);
            float ih = fmaxf(__fsub_rn(yy2, yy1), 0.f);
            float inter = __fmul_rn(iw, ih);
            float uni = __fsub_rn(__fadd_rn(ai, bar[j]), inter);
            float u = fmaxf(uni, 1e-9f);
            // exact: rn(inter/u) > 0.5  <=>  inter - 0.5u > u * 2^-25
            if (fmaf(-0.5f, u, inter) > u * 0x1p-25f)
                bits |= 1ull << (j - j0);
        }
        mat[i * 4 + w] = bits;
    }
    __syncthreads();

    if (threadIdx.x == 0) {
        unsigned long long s0 = 0, s1 = 0, s2 = 0, s3 = 0;
        for (int i = 0; i < T; i++) {
            unsigned long long sw = (i < 64) ? s0 : (i < 128) ? s1 : (i < 192) ? s2 : s3;
            bool kp = !((sw >> (i & 63)) & 1ull);
            keepA[i] = kp ? 1 : 0;
            if (kp) {
                s0 |= mat[i * 4 + 0];
                s1 |= mat[i * 4 + 1];
                s2 |= mat[i * 4 + 2];
                s3 |= mat[i * 4 + 3];
            }
        }
    }
    __syncthreads();

    float* o = out + (size_t)slice * TOPK * 5;
    for (int t = threadIdx.x; t < TOPK; t += nt) {
        bool kp = (t < T) && keepA[t];
        o[t * 5 + 0] = kp ? bx1[t] : 0.f;
        o[t * 5 + 1] = kp ? by1[t] : 0.f;
        o[t * 5 + 2] = kp ? bx2[t] : 0.f;
        o[t * 5 + 3] = kp ? by2[t] : 0.f;
        o[t * 5 + 4] = kp ? bsc[t] : 0.f;
    }
}

extern "C" void kernel_launch(void* const* d_in, const int* in_sizes, int n_in,
                              void* d_out, int out_size) {
    const float* conf    = (const float*)d_in[0];
    const float* loc     = (const float*)d_in[1];
    const float* anchors = (const float*)d_in[2];
    float* out = (float*)d_out;

    k_zero<<<(SLICES * NBIN + 255) / 256, 256>>>();
    k_score<<<(BB * NN) / 256, 256>>>(conf);
    k_hist<<<SLICES * 8, 256>>>();
    k_collect<<<SLICES * 8, 256>>>();
    k_selnms<<<SLICES, 512>>>(conf, loc, anchors, out);
}

// round 15
// speedup vs baseline: 1.1815x; 1.0145x over previous
#include <cuda_runtime.h>
#include <math.h>

#define BB 16
#define NN 65536
#define CC 21
#define NCLS 20
#define SLICES (BB*NCLS)
#define TOPK 200
#define WSEL 512            // selection window target; exact top-200 provably inside
#define TH_CONF 0.05f
#define CBUF 2048
#define NBIN 128

// Static scratch (no runtime allocation).
__device__ __align__(16) unsigned char g_bins[(size_t)SLICES * NN];  // 21 MB u8 bin image
__device__ unsigned g_hist[SLICES * NBIN];
__device__ int g_scnt[SLICES];
__device__ unsigned g_sv[SLICES * CBUF];
__device__ unsigned long long g_keys[SLICES * CBUF];                 // 5.2 MB exact keys

// ---------------------------------------------------------------------------
// XLA-GPU-replica softmax sum over 21 exps (proven bit-exact rounds 5-14).
// ---------------------------------------------------------------------------
__device__ __forceinline__ float tree_sum21(const float* e) {
    float b0 = __fadd_rn(__fadd_rn(e[0],  e[16]), e[8]);
    float b1 = __fadd_rn(__fadd_rn(e[1],  e[17]), e[9]);
    float b2 = __fadd_rn(__fadd_rn(e[2],  e[18]), e[10]);
    float b3 = __fadd_rn(__fadd_rn(e[3],  e[19]), e[11]);
    float b4 = __fadd_rn(__fadd_rn(e[4],  e[20]), e[12]);
    float b5 = __fadd_rn(e[5],  e[13]);
    float b6 = __fadd_rn(e[6],  e[14]);
    float b7 = __fadd_rn(e[7],  e[15]);
    float c0 = __fadd_rn(b0, b4);
    float c1 = __fadd_rn(b1, b5);
    float c2 = __fadd_rn(b2, b6);
    float c3 = __fadd_rn(b3, b7);
    float d0 = __fadd_rn(c0, c2);
    float d1 = __fadd_rn(c1, c3);
    return __fadd_rn(d0, d1);
}

__device__ __forceinline__ float rcp_approx(float x) {
    float r;
    asm("rcp.approx.f32 %0, %1;" : "=f"(r) : "f"(x));
    return r;
}

// Schraudolph exp: 1 FFMA + 1 CVT, rel err ~ +/-3%. Screening only.
__device__ __forceinline__ float exp_fast(float x) {
    int i = __float2int_rn(fmaf(x, 12102203.0f, 1064993216.0f));
    return __int_as_float(i);
}

__global__ void k_zero() {
    int t = blockIdx.x * blockDim.x + threadIdx.x;
    if (t < SLICES * NBIN) g_hist[t] = 0;
    if (t < SLICES) g_scnt[t] = 0;
}

// ---------------------------------------------------------------------------
// Kernel 1 (round-14 verbatim, proven): approx softmax -> u8 bin image.
// bin = clamp((v16 - 0x3D00) >> 3, 0..127); bin 0 is "don't care"
// (exact-valid entries have p~ >= 0.047 -> bin >= 8).
// ---------------------------------------------------------------------------
__global__ void k_score(const float* __restrict__ conf) {
    __shared__ __align__(16) float s[256 * CC];                 // 21504 B
    __shared__ __align__(16) unsigned char sb8[NCLS][256];      // 5120 B
    const int bpb = NN / 256;
    int b  = blockIdx.x / bpb;
    int a0 = (blockIdx.x % bpb) * 256;

    const float4* src = reinterpret_cast<const float4*>(conf + ((size_t)b * NN + a0) * CC);
    float4* ds = reinterpret_cast<float4*>(s);
    #pragma unroll
    for (int j = threadIdx.x; j < 256 * CC / 4; j += 256) ds[j] = src[j];
    __syncthreads();

    int t = threadIdx.x;
    float e[CC];
    float sum = 0.f;
    #pragma unroll
    for (int c = 0; c < CC; c++) {
        e[c] = exp_fast(s[t * CC + c]);     // stride 21: conflict-free
        sum += e[c];
    }
    float rinv = rcp_approx(sum);
    #pragma unroll
    for (int c = 1; c < CC; c++) {
        unsigned v16 = __float_as_uint(e[c] * rinv) >> 16;
        unsigned bin = 0;
        if (v16 >= 0x3D08u) {
            bin = (v16 - 0x3D00u) >> 3;
            if (bin > 127u) bin = 127u;
        }
        sb8[c - 1][t] = (unsigned char)bin;
    }
    __syncthreads();

    // copy-out bin image: 20 rows x 256 B = 320 uint4, coalesced
    const uint4* sbv = reinterpret_cast<const uint4*>(sb8);
    for (int k = threadIdx.x; k < NCLS * 16; k += 256) {
        int row = k >> 4, off = k & 15;
        int slice = b * NCLS + row;
        reinterpret_cast<uint4*>(g_bins + (size_t)slice * NN + a0)[off] = sbv[k];
    }
}

// ---------------------------------------------------------------------------
// Kernel 1b (round-14 verbatim): histogram pass over the bin image.
// ---------------------------------------------------------------------------
__global__ void k_hist() {
    int bid = blockIdx.x;
    int slice = bid >> 3, chunk = bid & 7;
    int t = threadIdx.x;

    __shared__ unsigned hist[NBIN];
    if (t < NBIN) hist[t] = 0;
    __syncthreads();

    const uint4* bv = reinterpret_cast<const uint4*>(g_bins + (size_t)slice * NN + chunk * 8192);
    for (int i = t; i < 512; i += 256) {
        uint4 q = bv[i];
        unsigned wds[4] = {q.x, q.y, q.z, q.w};
        #pragma unroll
        for (int h = 0; h < 4; h++) {
            unsigned w = wds[h];
            if (w) {
                #pragma unroll
                for (int byte = 0; byte < 4; byte++) {
                    unsigned bin = (w >> (byte * 8)) & 0xFFu;
                    if (bin) atomicAdd(&hist[bin], 1u);
                }
            }
        }
    }
    __syncthreads();

    if (t < NBIN && hist[t]) atomicAdd(&g_hist[slice * NBIN + t], hist[t]);
}

// ---------------------------------------------------------------------------
// Kernel 2 (round-14 verbatim, proven): survivor collection with
// warp-aggregated push.
// ---------------------------------------------------------------------------
__global__ void k_collect() {
    int bid = blockIdx.x;
    int slice = bid >> 3, chunk = bid & 7;
    int t = threadIdx.x;
    unsigned lane = t & 31u;

    __shared__ unsigned suf[NBIN];
    __shared__ int s_vth;

    if (t < NBIN) suf[t] = g_hist[slice * NBIN + t];
    if (t == 0) s_vth = 1;
    __syncthreads();
    for (int st = 1; st < NBIN; st <<= 1) {
        unsigned add = 0;
        if (t < NBIN && t + st < NBIN) add = suf[t + st];
        __syncthreads();
        if (t < NBIN) suf[t] += add;
        __syncthreads();
    }
    unsigned total = suf[1];
    unsigned target = total < WSEL ? total : WSEL;
    if (t >= 1 && t < NBIN && target > 0 && suf[t] >= target) atomicMax(&s_vth, t);
    __syncthreads();
    unsigned vth = (unsigned)s_vth;
    unsigned vth4 = vth * 0x01010101u;

    const uint4* bv = reinterpret_cast<const uint4*>(g_bins + (size_t)slice * NN + chunk * 8192);
    int base0 = chunk * 8192;
    for (int i = t; i < 512; i += 256) {
        uint4 q = bv[i];
        unsigned m0 = __vcmpgeu4(q.x, vth4);
        unsigned m1 = __vcmpgeu4(q.y, vth4);
        unsigned m2 = __vcmpgeu4(q.z, vth4);
        unsigned m3 = __vcmpgeu4(q.w, vth4);
        int cnt = (__popc(m0) + __popc(m1) + __popc(m2) + __popc(m3)) >> 3;

        int inc = cnt;
        #pragma unroll
        for (int off = 1; off < 32; off <<= 1) {
            int v = __shfl_up_sync(0xffffffffu, inc, off);
            if ((int)lane >= off) inc += v;
        }
        int wtot = __shfl_sync(0xffffffffu, inc, 31);
        int excl = inc - cnt;

        int base = 0;
        if (lane == 31u && wtot > 0) base = atomicAdd(&g_scnt[slice], wtot);
        base = __shfl_sync(0xffffffffu, base, 31);

        if (cnt) {
            int pos = base + excl;
            unsigned ms[4] = {m0, m1, m2, m3};
            #pragma unroll
            for (int h = 0; h < 4; h++) {
                unsigned m = ms[h];
                while (m) {
                    int byte = (__ffs(m) - 1) >> 3;
                    if (pos < CBUF)
                        g_sv[slice * CBUF + pos] = (unsigned)(base0 + i * 16 + h * 4 + byte);
                    pos++;
                    m &= ~(0xFFu << (byte * 8));
                }
            }
        }
    }
}

// ---------------------------------------------------------------------------
// Kernel 2b (NEW): exact recompute at 4 blocks/slice (1280 blocks total).
// Bit-exact pipeline unchanged; writes u64 keys to g_keys. Independent
// candidates -> scales with block count, hiding the scattered conf gathers.
// ---------------------------------------------------------------------------
__global__ void k_exact(const float* __restrict__ conf) {
    int slice = blockIdx.x >> 2;
    int c4    = blockIdx.x & 3;
    int b   = slice / NCLS;
    int cls = slice % NCLS + 1;

    int S = g_scnt[slice];
    if (S > CBUF) S = CBUF;
    int per = (S + 3) >> 2;
    int st = c4 * per;
    int en = st + per; if (en > S) en = S;

    for (int t = st + threadIdx.x; t < en; t += 128) {
        int idx = (int)g_sv[slice * CBUF + t];
        const float* row = conf + ((size_t)b * NN + idx) * CC;
        float v[CC];
        #pragma unroll
        for (int c = 0; c < CC; c++) v[c] = row[c];
        float mx = v[0];
        #pragma unroll
        for (int c = 1; c < CC; c++) mx = fmaxf(mx, v[c]);
        float ex[CC];
        #pragma unroll
        for (int c = 0; c < CC; c++) ex[c] = expf(__fsub_rn(v[c], mx));
        float sum = tree_sum21(ex);
        float p = __fdiv_rn(ex[cls], sum);
        g_keys[slice * CBUF + t] = (p >= TH_CONF)
            ? (((unsigned long long)__float_as_uint(p) << 16) |
               (unsigned long long)(65535 - idx))
            : 0ull;
    }
}

// ---------------------------------------------------------------------------
// Kernel 3: sort + NMS (256 threads; sort and NMS bodies proven verbatim).
//  (1) load exact keys, pad, bitonic sort descending (score desc, idx asc)
//  (2) decode top-200 (bit-exact), triangle IoU bitmask (division-free exact
//      predicate), serial greedy scan, [200,5] output.
// ---------------------------------------------------------------------------
__global__ void k_sortnms(const float* __restrict__ loc,
                          const float* __restrict__ anchors,
                          float* __restrict__ out) {
    int slice = blockIdx.x;
    int b = slice / NCLS;

    __shared__ unsigned long long skeys[CBUF];   // 16 KB
    __shared__ float bx1[TOPK], by1[TOPK], bx2[TOPK], by2[TOPK], bar[TOPK], bsc[TOPK];
    __shared__ unsigned long long mat[TOPK * 4];
    __shared__ unsigned char keepA[TOPK];

    int S = g_scnt[slice];
    if (S > CBUF) S = CBUF;

    for (int t = threadIdx.x; t < S; t += 256)
        skeys[t] = g_keys[slice * CBUF + t];
    int P = 256; while (P < S) P <<= 1;
    for (int i = S + threadIdx.x; i < P; i += 256) skeys[i] = 0ull;
    __syncthreads();

    // bitonic sort, descending
    for (int k = 2; k <= P; k <<= 1) {
        for (int j = k >> 1; j > 0; j >>= 1) {
            for (int i = threadIdx.x; i < P; i += 256) {
                int l = i ^ j;
                if (l > i) {
                    unsigned long long a = skeys[i], c = skeys[l];
                    bool desc = ((i & k) == 0);
                    if (desc ? (a < c) : (a > c)) { skeys[i] = c; skeys[l] = a; }
                }
            }
            __syncthreads();
        }
    }

    int T = __syncthreads_count((threadIdx.x < TOPK) && (skeys[threadIdx.x] != 0ull));

    // decode (bit-exact)
    for (int t = threadIdx.x; t < T; t += 256) {
        unsigned long long key = skeys[t];
        int idx = 65535 - (int)(key & 0xFFFFull);
        float sc = __uint_as_float((unsigned)(key >> 16));
        float4 l = reinterpret_cast<const float4*>(loc)[(size_t)b * NN + idx];
        float4 a = reinterpret_cast<const float4*>(anchors)[idx];
        float cx = __fadd_rn(a.x, __fmul_rn(__fmul_rn(l.x, 0.1f), a.z));
        float cy = __fadd_rn(a.y, __fmul_rn(__fmul_rn(l.y, 0.1f), a.w));
        float w  = __fmul_rn(a.z, expf(__fmul_rn(l.z, 0.2f)));
        float h  = __fmul_rn(a.w, expf(__fmul_rn(l.w, 0.2f)));
        float x1 = __fsub_rn(cx, __fmul_rn(0.5f, w));
        float y1 = __fsub_rn(cy, __fmul_rn(0.5f, h));
        float x2 = __fadd_rn(cx, __fmul_rn(0.5f, w));
        float y2 = __fadd_rn(cy, __fmul_rn(0.5f, h));
        bx1[t] = x1; by1[t] = y1; bx2[t] = x2; by2[t] = y2;
        bar[t] = __fmul_rn(fmaxf(__fsub_rn(x2, x1), 0.f),
                           fmaxf(__fsub_rn(y2, y1), 0.f));
        bsc[t] = sc;
    }
    __syncthreads();

    // upper triangle only: the greedy scan only consumes bits j > i
    for (int task = threadIdx.x; task < T * 4; task += 256) {
        int i = task >> 2, w = task & 3;
        unsigned long long bits = 0;
        int j0 = w * 64;
        int j1 = j0 + 64 < T ? j0 + 64 : T;
        int js = j0 > i + 1 ? j0 : i + 1;
        float x1i = bx1[i], y1i = by1[i], x2i = bx2[i], y2i = by2[i], ai = bar[i];
        for (int j = js; j < j1; j++) {
            float xx1 = fmaxf(x1i, bx1[j]);
            float yy1 = fmaxf(y1i, by1[j]);
            float xx2 = fminf(x2i, bx2[j]);
            float yy2 = fminf(y2i, by2[j]);
            float iw = fmaxf(__fsub_rn(xx2, xx1), 0.f);
            float ih = fmaxf(__fsub_rn(yy2, yy1), 0.f);
            float inter = __fmul_rn(iw, ih);
            float uni = __fsub_rn(__fadd_rn(ai, bar[j]), inter);
            float u = fmaxf(uni, 1e-9f);
            // exact: rn(inter/u) > 0.5  <=>  inter - 0.5u > u * 2^-25
            if (fmaf(-0.5f, u, inter) > u * 0x1p-25f)
                bits |= 1ull << (j - j0);
        }
        mat[i * 4 + w] = bits;
    }
    __syncthreads();

    if (threadIdx.x == 0) {
        unsigned long long s0 = 0, s1 = 0, s2 = 0, s3 = 0;
        for (int i = 0; i < T; i++) {
            unsigned long long sw = (i < 64) ? s0 : (i < 128) ? s1 : (i < 192) ? s2 : s3;
            bool kp = !((sw >> (i & 63)) & 1ull);
            keepA[i] = kp ? 1 : 0;
            if (kp) {
                s0 |= mat[i * 4 + 0];
                s1 |= mat[i * 4 + 1];
                s2 |= mat[i * 4 + 2];
                s3 |= mat[i * 4 + 3];
            }
        }
    }
    __syncthreads();

    float* o = out + (size_t)slice * TOPK * 5;
    for (int t = threadIdx.x; t < TOPK; t += 256) {
        bool kp = (t < T) && keepA[t];
        o[t * 5 + 0] = kp ? bx1[t] : 0.f;
        o[t * 5 + 1] = kp ? by1[t] : 0.f;
        o[t * 5 + 2] = kp ? bx2[t] : 0.f;
        o[t * 5 + 3] = kp ? by2[t] : 0.f;
        o[t * 5 + 4] = kp ? bsc[t] : 0.f;
    }
}

extern "C" void kernel_launch(void* const* d_in, const int* in_sizes, int n_in,
                              void* d_out, int out_size) {
    const float* conf    = (const float*)d_in[0];
    const float* loc     = (const float*)d_in[1];
    const float* anchors = (const float*)d_in[2];
    float* out = (float*)d_out;

    k_zero<<<(SLICES * NBIN + 255) / 256, 256>>>();
    k_score<<<(BB * NN) / 256, 256>>>(conf);
    k_hist<<<SLICES * 8, 256>>>();
    k_collect<<<SLICES * 8, 256>>>();
    k_exact<<<SLICES * 4, 128>>>(conf);
    k_sortnms<<<SLICES, 256>>>(loc, anchors, out);
}

// round 17
// speedup vs baseline: 1.2721x; 1.0767x over previous
#include <cuda_runtime.h>
#include <math.h>

#define BB 16
#define NN 65536
#define CC 21
#define NCLS 20
#define SLICES (BB*NCLS)
#define TOPK 200
#define WSEL 512            // selection window target; exact top-200 provably inside
#define TH_CONF 0.05f
#define CBUF 2048
#define NBIN 128

// Static scratch (no runtime allocation).
__device__ __align__(16) unsigned char g_bins[(size_t)SLICES * NN];  // 21 MB u8 bin image
__device__ unsigned g_hist[SLICES * NBIN];
__device__ int g_scnt[SLICES];
__device__ unsigned g_sv[SLICES * CBUF];
__device__ unsigned long long g_keys[SLICES * CBUF];                 // 5.2 MB exact keys
__device__ unsigned long long g_top[SLICES * TOPK];
__device__ int g_topcnt[SLICES];
__device__ __align__(16) float4 g_boxes[SLICES * TOPK];              // 1 MB decoded boxes
__device__ float g_barA[SLICES * TOPK];
__device__ float g_bscA[SLICES * TOPK];
__device__ unsigned long long g_mat[SLICES * TOPK * 4];              // 2 MB IoU bitmask

// ---------------------------------------------------------------------------
// XLA-GPU-replica softmax sum over 21 exps (proven bit-exact rounds 5-15).
// ---------------------------------------------------------------------------
__device__ __forceinline__ float tree_sum21(const float* e) {
    float b0 = __fadd_rn(__fadd_rn(e[0],  e[16]), e[8]);
    float b1 = __fadd_rn(__fadd_rn(e[1],  e[17]), e[9]);
    float b2 = __fadd_rn(__fadd_rn(e[2],  e[18]), e[10]);
    float b3 = __fadd_rn(__fadd_rn(e[3],  e[19]), e[11]);
    float b4 = __fadd_rn(__fadd_rn(e[4],  e[20]), e[12]);
    float b5 = __fadd_rn(e[5],  e[13]);
    float b6 = __fadd_rn(e[6],  e[14]);
    float b7 = __fadd_rn(e[7],  e[15]);
    float c0 = __fadd_rn(b0, b4);
    float c1 = __fadd_rn(b1, b5);
    float c2 = __fadd_rn(b2, b6);
    float c3 = __fadd_rn(b3, b7);
    float d0 = __fadd_rn(c0, c2);
    float d1 = __fadd_rn(c1, c3);
    return __fadd_rn(d0, d1);
}

__device__ __forceinline__ float rcp_approx(float x) {
    float r;
    asm("rcp.approx.f32 %0, %1;" : "=f"(r) : "f"(x));
    return r;
}

// Schraudolph exp: 1 FFMA + 1 CVT, rel err ~ +/-3%. Screening only.
__device__ __forceinline__ float exp_fast(float x) {
    int i = __float2int_rn(fmaf(x, 12102203.0f, 1064993216.0f));
    return __int_as_float(i);
}

__global__ void k_zero() {
    int t = blockIdx.x * blockDim.x + threadIdx.x;
    if (t < SLICES * NBIN) g_hist[t] = 0;
    if (t < SLICES) g_scnt[t] = 0;
}

// ---------------------------------------------------------------------------
// Kernel 1 (proven verbatim): approx softmax -> u8 bin image.
// ---------------------------------------------------------------------------
__global__ void k_score(const float* __restrict__ conf) {
    __shared__ __align__(16) float s[256 * CC];
    __shared__ __align__(16) unsigned char sb8[NCLS][256];
    const int bpb = NN / 256;
    int b  = blockIdx.x / bpb;
    int a0 = (blockIdx.x % bpb) * 256;

    const float4* src = reinterpret_cast<const float4*>(conf + ((size_t)b * NN + a0) * CC);
    float4* ds = reinterpret_cast<float4*>(s);
    #pragma unroll
    for (int j = threadIdx.x; j < 256 * CC / 4; j += 256) ds[j] = src[j];
    __syncthreads();

    int t = threadIdx.x;
    float e[CC];
    float sum = 0.f;
    #pragma unroll
    for (int c = 0; c < CC; c++) {
        e[c] = exp_fast(s[t * CC + c]);
        sum += e[c];
    }
    float rinv = rcp_approx(sum);
    #pragma unroll
    for (int c = 1; c < CC; c++) {
        unsigned v16 = __float_as_uint(e[c] * rinv) >> 16;
        unsigned bin = 0;
        if (v16 >= 0x3D08u) {
            bin = (v16 - 0x3D00u) >> 3;
            if (bin > 127u) bin = 127u;
        }
        sb8[c - 1][t] = (unsigned char)bin;
    }
    __syncthreads();

    const uint4* sbv = reinterpret_cast<const uint4*>(sb8);
    for (int k = threadIdx.x; k < NCLS * 16; k += 256) {
        int row = k >> 4, off = k & 15;
        int slice = b * NCLS + row;
        reinterpret_cast<uint4*>(g_bins + (size_t)slice * NN + a0)[off] = sbv[k];
    }
}

// ---------------------------------------------------------------------------
// Kernel 1b (proven verbatim): histogram pass over the bin image.
// ---------------------------------------------------------------------------
__global__ void k_hist() {
    int bid = blockIdx.x;
    int slice = bid >> 3, chunk = bid & 7;
    int t = threadIdx.x;

    __shared__ unsigned hist[NBIN];
    if (t < NBIN) hist[t] = 0;
    __syncthreads();

    const uint4* bv = reinterpret_cast<const uint4*>(g_bins + (size_t)slice * NN + chunk * 8192);
    for (int i = t; i < 512; i += 256) {
        uint4 q = bv[i];
        unsigned wds[4] = {q.x, q.y, q.z, q.w};
        #pragma unroll
        for (int h = 0; h < 4; h++) {
            unsigned w = wds[h];
            if (w) {
                #pragma unroll
                for (int byte = 0; byte < 4; byte++) {
                    unsigned bin = (w >> (byte * 8)) & 0xFFu;
                    if (bin) atomicAdd(&hist[bin], 1u);
                }
            }
        }
    }
    __syncthreads();

    if (t < NBIN && hist[t]) atomicAdd(&g_hist[slice * NBIN + t], hist[t]);
}

// ---------------------------------------------------------------------------
// Kernel 2 (proven verbatim): survivor collection, warp-aggregated push.
// ---------------------------------------------------------------------------
__global__ void k_collect() {
    int bid = blockIdx.x;
    int slice = bid >> 3, chunk = bid & 7;
    int t = threadIdx.x;
    unsigned lane = t & 31u;

    __shared__ unsigned suf[NBIN];
    __shared__ int s_vth;

    if (t < NBIN) suf[t] = g_hist[slice * NBIN + t];
    if (t == 0) s_vth = 1;
    __syncthreads();
    for (int st = 1; st < NBIN; st <<= 1) {
        unsigned add = 0;
        if (t < NBIN && t + st < NBIN) add = suf[t + st];
        __syncthreads();
        if (t < NBIN) suf[t] += add;
        __syncthreads();
    }
    unsigned total = suf[1];
    unsigned target = total < WSEL ? total : WSEL;
    if (t >= 1 && t < NBIN && target > 0 && suf[t] >= target) atomicMax(&s_vth, t);
    __syncthreads();
    unsigned vth = (unsigned)s_vth;
    unsigned vth4 = vth * 0x01010101u;

    const uint4* bv = reinterpret_cast<const uint4*>(g_bins + (size_t)slice * NN + chunk * 8192);
    int base0 = chunk * 8192;
    for (int i = t; i < 512; i += 256) {
        uint4 q = bv[i];
        unsigned m0 = __vcmpgeu4(q.x, vth4);
        unsigned m1 = __vcmpgeu4(q.y, vth4);
        unsigned m2 = __vcmpgeu4(q.z, vth4);
        unsigned m3 = __vcmpgeu4(q.w, vth4);
        int cnt = (__popc(m0) + __popc(m1) + __popc(m2) + __popc(m3)) >> 3;

        int inc = cnt;
        #pragma unroll
        for (int off = 1; off < 32; off <<= 1) {
            int v = __shfl_up_sync(0xffffffffu, inc, off);
            if ((int)lane >= off) inc += v;
        }
        int wtot = __shfl_sync(0xffffffffu, inc, 31);
        int excl = inc - cnt;

        int base = 0;
        if (lane == 31u && wtot > 0) base = atomicAdd(&g_scnt[slice], wtot);
        base = __shfl_sync(0xffffffffu, base, 31);

        if (cnt) {
            int pos = base + excl;
            unsigned ms[4] = {m0, m1, m2, m3};
            #pragma unroll
            for (int h = 0; h < 4; h++) {
                unsigned m = ms[h];
                while (m) {
                    int byte = (__ffs(m) - 1) >> 3;
                    if (pos < CBUF)
                        g_sv[slice * CBUF + pos] = (unsigned)(base0 + i * 16 + h * 4 + byte);
                    pos++;
                    m &= ~(0xFFu << (byte * 8));
                }
            }
        }
    }
}

// ---------------------------------------------------------------------------
// Kernel 2b (proven verbatim): exact recompute at 4 blocks/slice.
// ---------------------------------------------------------------------------
__global__ void k_exact(const float* __restrict__ conf) {
    int slice = blockIdx.x >> 2;
    int c4    = blockIdx.x & 3;
    int b   = slice / NCLS;
    int cls = slice % NCLS + 1;

    int S = g_scnt[slice];
    if (S > CBUF) S = CBUF;
    int per = (S + 3) >> 2;
    int st = c4 * per;
    int en = st + per; if (en > S) en = S;

    for (int t = st + threadIdx.x; t < en; t += 128) {
        int idx = (int)g_sv[slice * CBUF + t];
        const float* row = conf + ((size_t)b * NN + idx) * CC;
        float v[CC];
        #pragma unroll
        for (int c = 0; c < CC; c++) v[c] = row[c];
        float mx = v[0];
        #pragma unroll
        for (int c = 1; c < CC; c++) mx = fmaxf(mx, v[c]);
        float ex[CC];
        #pragma unroll
        for (int c = 0; c < CC; c++) ex[c] = expf(__fsub_rn(v[c], mx));
        float sum = tree_sum21(ex);
        float p = __fdiv_rn(ex[cls], sum);
        g_keys[slice * CBUF + t] = (p >= TH_CONF)
            ? (((unsigned long long)__float_as_uint(p) << 16) |
               (unsigned long long)(65535 - idx))
            : 0ull;
    }
}

// ---------------------------------------------------------------------------
// Kernel 3: plain full bitonic sort (round-12 proven structure, NO cutoff).
// Load keys, pad, sort descending, write sorted top-200 + count.
// ---------------------------------------------------------------------------
__global__ void k_sort() {
    int slice = blockIdx.x;

    __shared__ unsigned long long skeys[CBUF];   // 16 KB

    int S = g_scnt[slice];
    if (S > CBUF) S = CBUF;

    for (int t = threadIdx.x; t < S; t += 256)
        skeys[t] = g_keys[slice * CBUF + t];
    int P = 256; while (P < S) P <<= 1;
    for (int i = S + threadIdx.x; i < P; i += 256) skeys[i] = 0ull;
    __syncthreads();

    // bitonic sort, descending
    for (int k = 2; k <= P; k <<= 1) {
        for (int j = k >> 1; j > 0; j >>= 1) {
            for (int i = threadIdx.x; i < P; i += 256) {
                int l = i ^ j;
                if (l > i) {
                    unsigned long long a = skeys[i], c = skeys[l];
                    bool desc = ((i & k) == 0);
                    if (desc ? (a < c) : (a > c)) { skeys[i] = c; skeys[l] = a; }
                }
            }
            __syncthreads();
        }
    }

    int T = __syncthreads_count((threadIdx.x < TOPK) && (skeys[threadIdx.x] != 0ull));
    for (int t = threadIdx.x; t < T; t += 256) g_top[slice * TOPK + t] = skeys[t];
    if (threadIdx.x == 0) g_topcnt[slice] = T;
}

// ---------------------------------------------------------------------------
// Kernel 4: decode sorted top-200 to global (bit-exact decode body verbatim),
// 4 blocks/slice x 64 threads (latency-hidden gathers).
// ---------------------------------------------------------------------------
__global__ void k_boxes(const float* __restrict__ loc,
                        const float* __restrict__ anchors) {
    int slice = blockIdx.x >> 2;
    int c4    = blockIdx.x & 3;
    int b = slice / NCLS;
    int T = g_topcnt[slice];

    int t = c4 * 50 + threadIdx.x;
    if (threadIdx.x < 50 && t < T) {
        unsigned long long key = g_top[slice * TOPK + t];
        int idx = 65535 - (int)(key & 0xFFFFull);
        float sc = __uint_as_float((unsigned)(key >> 16));
        float4 l = reinterpret_cast<const float4*>(loc)[(size_t)b * NN + idx];
        float4 a = reinterpret_cast<const float4*>(anchors)[idx];
        float cx = __fadd_rn(a.x, __fmul_rn(__fmul_rn(l.x, 0.1f), a.z));
        float cy = __fadd_rn(a.y, __fmul_rn(__fmul_rn(l.y, 0.1f), a.w));
        float w  = __fmul_rn(a.z, expf(__fmul_rn(l.z, 0.2f)));
        float h  = __fmul_rn(a.w, expf(__fmul_rn(l.w, 0.2f)));
        float x1 = __fsub_rn(cx, __fmul_rn(0.5f, w));
        float y1 = __fsub_rn(cy, __fmul_rn(0.5f, h));
        float x2 = __fadd_rn(cx, __fmul_rn(0.5f, w));
        float y2 = __fadd_rn(cy, __fmul_rn(0.5f, h));
        g_boxes[slice * TOPK + t] = make_float4(x1, y1, x2, y2);
        g_barA[slice * TOPK + t] = __fmul_rn(fmaxf(__fsub_rn(x2, x1), 0.f),
                                             fmaxf(__fsub_rn(y2, y1), 0.f));
        g_bscA[slice * TOPK + t] = sc;
    }
}

// ---------------------------------------------------------------------------
// Kernel 5: IoU bitmask build, 4 blocks/slice (one 64-bit word each),
// division-free exact predicate verbatim. Boxes staged in smem.
// ---------------------------------------------------------------------------
__global__ void k_mat() {
    int slice = blockIdx.x >> 2;
    int w     = blockIdx.x & 3;
    int T = g_topcnt[slice];

    __shared__ __align__(16) float4 sbx[TOPK];
    __shared__ float sbar[TOPK];

    for (int t = threadIdx.x; t < T; t += 256) {
        sbx[t]  = g_boxes[slice * TOPK + t];
        sbar[t] = g_barA[slice * TOPK + t];
    }
    __syncthreads();

    int j0 = w * 64;
    int j1 = j0 + 64 < T ? j0 + 64 : T;
    for (int i = threadIdx.x; i < T; i += 256) {
        unsigned long long bits = 0;
        int js = j0 > i + 1 ? j0 : i + 1;
        float4 Bi = sbx[i];
        float ai = sbar[i];
        for (int j = js; j < j1; j++) {
            float4 Bj = sbx[j];
            float xx1 = fmaxf(Bi.x, Bj.x);
            float yy1 = fmaxf(Bi.y, Bj.y);
            float xx2 = fminf(Bi.z, Bj.z);
            float yy2 = fminf(Bi.w, Bj.w);
            float iw = fmaxf(__fsub_rn(xx2, xx1), 0.f);
            float ih = fmaxf(__fsub_rn(yy2, yy1), 0.f);
            float inter = __fmul_rn(iw, ih);
            float uni = __fsub_rn(__fadd_rn(ai, sbar[j]), inter);
            float u = fmaxf(uni, 1e-9f);
            // exact: rn(inter/u) > 0.5  <=>  inter - 0.5u > u * 2^-25
            if (fmaf(-0.5f, u, inter) > u * 0x1p-25f)
                bits |= 1ull << (j - j0);
        }
        g_mat[(slice * TOPK + i) * 4 + w] = bits;
    }
}

// ---------------------------------------------------------------------------
// Kernel 6: serial greedy scan (verbatim) + output write.
// ---------------------------------------------------------------------------
__global__ void k_scan(float* __restrict__ out) {
    int slice = blockIdx.x;
    int T = g_topcnt[slice];

    __shared__ unsigned long long mat[TOPK * 4];
    __shared__ unsigned char keepA[TOPK];

    for (int k = threadIdx.x; k < T * 4; k += 256)
        mat[k] = g_mat[slice * TOPK * 4 + k];
    __syncthreads();

    if (threadIdx.x == 0) {
        unsigned long long s0 = 0, s1 = 0, s2 = 0, s3 = 0;
        for (int i = 0; i < T; i++) {
            unsigned long long sw = (i < 64) ? s0 : (i < 128) ? s1 : (i < 192) ? s2 : s3;
            bool kp = !((sw >> (i & 63)) & 1ull);
            keepA[i] = kp ? 1 : 0;
            if (kp) {
                s0 |= mat[i * 4 + 0];
                s1 |= mat[i * 4 + 1];
                s2 |= mat[i * 4 + 2];
                s3 |= mat[i * 4 + 3];
            }
        }
    }
    __syncthreads();

    float* o = out + (size_t)slice * TOPK * 5;
    for (int t = threadIdx.x; t < TOPK; t += 256) {
        bool kp = (t < T) && keepA[t];
        float4 Bt = kp ? g_boxes[slice * TOPK + t] : make_float4(0.f, 0.f, 0.f, 0.f);
        float sc = kp ? g_bscA[slice * TOPK + t] : 0.f;
        o[t * 5 + 0] = Bt.x;
        o[t * 5 + 1] = Bt.y;
        o[t * 5 + 2] = Bt.z;
        o[t * 5 + 3] = Bt.w;
        o[t * 5 + 4] = sc;
    }
}

extern "C" void kernel_launch(void* const* d_in, const int* in_sizes, int n_in,
                              void* d_out, int out_size) {
    const float* conf    = (const float*)d_in[0];
    const float* loc     = (const float*)d_in[1];
    const float* anchors = (const float*)d_in[2];
    float* out = (float*)d_out;

    k_zero<<<(SLICES * NBIN + 255) / 256, 256>>>();
    k_score<<<(BB * NN) / 256, 256>>>(conf);
    k_hist<<<SLICES * 8, 256>>>();
    k_collect<<<SLICES * 8, 256>>>();
    k_exact<<<SLICES * 4, 128>>>(conf);
    k_sort<<<SLICES, 256>>>();
    k_boxes<<<SLICES * 4, 64>>>(loc, anchors);
    k_mat<<<SLICES * 4, 256>>>();
    k_scan<<<SLICES, 256>>>(out);
}